// round 1
// baseline (speedup 1.0000x reference)
#include <cuda_runtime.h>
#include <math.h>

#define L6 6
#define BB 32
#define QQ 900
#define DD 256
#define MM (BB*QQ)                 // 28800 tokens per level
#define MD ((size_t)MM*(size_t)DD) // per-level elements

// Scratch (device globals: allocation-free per harness rules)
__device__ float g_x1[(size_t)L6*MM*DD];
__device__ float g_x2[(size_t)L6*MM*DD];
__device__ float g_y1[(size_t)L6*MM*DD];
__device__ float g_y2[(size_t)L6*MM*DD];

__device__ __forceinline__ float warp_sum(float v) {
#pragma unroll
    for (int off = 16; off; off >>= 1)
        v += __shfl_xor_sync(0xffffffffu, v, off);
    return v;
}

// One block computes a 64-row x 256-col output tile (full N => LN can be fused).
// blockIdx.y: 0 = cls path (Linear+LN+ReLU), 1 = reg path (Linear+ReLU)
// blockIdx.z: level
// stage 0: A = hs[l]; stage 1: A = g_x1/g_y1
__global__ __launch_bounds__(256, 2)
void fused_mlp_kernel(int stage,
                      const float* __restrict__ hs,
                      const float* __restrict__ Wc, const float* __restrict__ bc,
                      const float* __restrict__ gc, const float* __restrict__ betac,
                      const float* __restrict__ Wr, const float* __restrict__ br)
{
    const int l    = blockIdx.z;
    const int path = blockIdx.y;
    const int m0   = blockIdx.x * 64;
    const int t    = threadIdx.x;
    const int lane = t & 31, warp = t >> 5;

    const float* A;
    float* O;
    if (stage == 0) {
        A = hs + (size_t)l * MD;                       // hs[l] is [Q*B, D] contiguous, m = q*B+b
        O = (path ? g_y1 : g_x1) + (size_t)l * MD;
    } else {
        A = (path ? g_y1 : g_x1) + (size_t)l * MD;
        O = (path ? g_y2 : g_x2) + (size_t)l * MD;
    }
    const float* W    = (path ? Wr : Wc) + (size_t)l * DD * DD;   // [K,N] row-major
    const float* bias = (path ? br : bc) + l * DD;

    __shared__ float As[32][66];    // [k][m] transposed A tile (66: 8B-aligned rows, pad)
    __shared__ float Bs[32][256];   // [k][n]

    // accumulators: rows paired in f32x2 (p -> rows 2p,2p+1), 8 cols (lane + 32*j)
    unsigned long long acc[4][8];
#pragma unroll
    for (int p = 0; p < 4; ++p)
#pragma unroll
        for (int j = 0; j < 8; ++j) acc[p][j] = 0ull;

    for (int kt = 0; kt < 8; ++kt) {
        // Load A tile 64x32, transpose into As[k][m]
#pragma unroll
        for (int s = 0; s < 2; ++s) {
            int id = t + 256 * s;            // 0..511 float4s
            int r  = id >> 3;                // 0..63
            int c4 = (id & 7) << 2;          // 0..28
            const float4 f = *(const float4*)&A[(size_t)(m0 + r) * DD + kt * 32 + c4];
            As[c4 + 0][r] = f.x;
            As[c4 + 1][r] = f.y;
            As[c4 + 2][r] = f.z;
            As[c4 + 3][r] = f.w;
        }
        // Load B tile 32x256 (direct copy)
#pragma unroll
        for (int s = 0; s < 8; ++s) {
            int id = t + 256 * s;            // 0..2047 float4s
            int kr = id >> 6;                // 0..31
            int c4 = (id & 63) << 2;         // 0..252
            *(float4*)&Bs[kr][c4] = *(const float4*)&W[(size_t)(kt * 32 + kr) * DD + c4];
        }
        __syncthreads();

#pragma unroll 8
        for (int kk = 0; kk < 32; ++kk) {
            unsigned long long a2[4];
#pragma unroll
            for (int p = 0; p < 4; ++p)      // LDS.64 broadcast (all lanes same addr)
                a2[p] = *(const unsigned long long*)&As[kk][warp * 8 + 2 * p];
#pragma unroll
            for (int j = 0; j < 8; ++j) {
                float bj = Bs[kk][lane + 32 * j];   // conflict-free: bank == lane
                unsigned long long b2;
                asm("mov.b64 %0, {%1, %1};" : "=l"(b2) : "f"(bj));
#pragma unroll
                for (int p = 0; p < 4; ++p)
                    asm("fma.rn.f32x2 %0, %1, %2, %0;"
                        : "+l"(acc[p][j]) : "l"(a2[p]), "l"(b2));
            }
        }
        __syncthreads();
    }

    // Unpack accumulators: v[i][j], i = local row, cols = lane + 32*j
    float v[8][8];
#pragma unroll
    for (int p = 0; p < 4; ++p)
#pragma unroll
        for (int j = 0; j < 8; ++j)
            asm("mov.b64 {%0, %1}, %2;"
                : "=f"(v[2 * p][j]), "=f"(v[2 * p + 1][j]) : "l"(acc[p][j]));

    float bv[8];
#pragma unroll
    for (int j = 0; j < 8; ++j) bv[j] = bias[lane + 32 * j];

    if (path == 0) {
        // bias -> LayerNorm (over the 256 cols of each row) -> gamma,beta -> ReLU
        float gv[8], bev[8];
        const float* gp = gc    + l * DD;
        const float* bp = betac + l * DD;
#pragma unroll
        for (int j = 0; j < 8; ++j) { gv[j] = gp[lane + 32 * j]; bev[j] = bp[lane + 32 * j]; }
#pragma unroll
        for (int i = 0; i < 8; ++i) {
            float s1 = 0.f, s2 = 0.f;
#pragma unroll
            for (int j = 0; j < 8; ++j) {
                float x = v[i][j] + bv[j];
                v[i][j] = x;
                s1 += x; s2 += x * x;
            }
            s1 = warp_sum(s1);
            s2 = warp_sum(s2);
            float mean = s1 * (1.0f / 256.0f);
            float var  = s2 * (1.0f / 256.0f) - mean * mean;
            float rs   = rsqrtf(var + 1e-5f);
            float* orow = O + (size_t)(m0 + warp * 8 + i) * DD;
#pragma unroll
            for (int j = 0; j < 8; ++j) {
                float y = (v[i][j] - mean) * rs * gv[j] + bev[j];
                orow[lane + 32 * j] = fmaxf(y, 0.f);
            }
        }
    } else {
        // bias -> ReLU
#pragma unroll
        for (int i = 0; i < 8; ++i) {
            float* orow = O + (size_t)(m0 + warp * 8 + i) * DD;
#pragma unroll
            for (int j = 0; j < 8; ++j)
                orow[lane + 32 * j] = fmaxf(v[i][j] + bv[j], 0.f);
        }
    }
}

// Head: warp per (l, token). cls = x2 @ cw3 + cb3 ; tmp = y2 @ rw3 + rb3 ; coord epilogue.
__global__ __launch_bounds__(256)
void head_kernel(const float* __restrict__ cw3, const float* __restrict__ cb3,
                 const float* __restrict__ rw3, const float* __restrict__ rb3,
                 const float* __restrict__ init_ref, const float* __restrict__ inter_ref,
                 float* __restrict__ out)
{
    __shared__ float Wc[10][256];   // transposed: Wc[c][k]
    __shared__ float Wr[10][256];
    const int t = threadIdx.x, lane = t & 31, warp = t >> 5;
    const int l = blockIdx.x / 3600;                // 3600 blocks per level (28800/8)

    for (int idx = t; idx < 2560; idx += 256) {
        int k = idx / 10, c = idx - k * 10;
        Wc[c][k] = cw3[l * 2560 + idx];
        Wr[c][k] = rw3[l * 2560 + idx];
    }
    __syncthreads();

    const int m = (blockIdx.x % 3600) * 8 + warp;   // token in (q*B+b) order
    const int q = m >> 5, b = m & 31;
    const float* xrow = g_x2 + ((size_t)l * MM + m) * DD;
    const float* yrow = g_y2 + ((size_t)l * MM + m) * DD;

    float xa[10], ya[10];
#pragma unroll
    for (int c = 0; c < 10; ++c) { xa[c] = 0.f; ya[c] = 0.f; }
#pragma unroll
    for (int jj = 0; jj < 8; ++jj) {
        int k = lane + 32 * jj;
        float xv = xrow[k], yv = yrow[k];
#pragma unroll
        for (int c = 0; c < 10; ++c) {
            xa[c] = fmaf(xv, Wc[c][k], xa[c]);
            ya[c] = fmaf(yv, Wr[c][k], ya[c]);
        }
    }
#pragma unroll
    for (int c = 0; c < 10; ++c) { xa[c] = warp_sum(xa[c]); ya[c] = warp_sum(ya[c]); }

    if (lane == 0) {
        const size_t base = (((size_t)l * BB + b) * QQ + q) * 10;
        float tmp[10];
#pragma unroll
        for (int c = 0; c < 10; ++c) {
            out[base + c] = xa[c] + cb3[l * 10 + c];   // cls scores
            tmp[c] = ya[c] + rb3[l * 10 + c];
        }
        const float* rp = (l == 0)
            ? (init_ref + ((size_t)b * QQ + q) * 3)
            : (inter_ref + (((size_t)(l - 1) * BB + b) * QQ + q) * 3);
        float r[3];
#pragma unroll
        for (int i = 0; i < 3; ++i) {
            float x  = fminf(fmaxf(rp[i], 0.f), 1.f);
            float x1 = fmaxf(x, 1e-5f);
            float x2 = fmaxf(1.f - x, 1e-5f);
            r[i] = logf(x1 / x2);                      // inverse sigmoid
        }
        float xy0 = 1.f / (1.f + expf(-(tmp[0] + r[0])));
        float xy1 = 1.f / (1.f + expf(-(tmp[1] + r[1])));
        float z   = 1.f / (1.f + expf(-(tmp[4] + r[2])));
        float* co = out + (size_t)L6 * BB * QQ * 10 + base;   // bbox preds
        co[0] = xy0 * 102.4f - 51.2f;
        co[1] = xy1 * 102.4f - 51.2f;
        co[2] = tmp[2];
        co[3] = tmp[3];
        co[4] = z * 8.0f - 5.0f;
        co[5] = tmp[5]; co[6] = tmp[6]; co[7] = tmp[7]; co[8] = tmp[8]; co[9] = tmp[9];
    }
}

extern "C" void kernel_launch(void* const* d_in, const int* in_sizes, int n_in,
                              void* d_out, int out_size) {
    const float* hs        = (const float*)d_in[0];
    const float* init_ref  = (const float*)d_in[1];
    const float* inter_ref = (const float*)d_in[2];
    const float* cls_w1    = (const float*)d_in[3];
    const float* cls_b1    = (const float*)d_in[4];
    const float* ln1_g     = (const float*)d_in[5];
    const float* ln1_b     = (const float*)d_in[6];
    const float* cls_w2    = (const float*)d_in[7];
    const float* cls_b2    = (const float*)d_in[8];
    const float* ln2_g     = (const float*)d_in[9];
    const float* ln2_b     = (const float*)d_in[10];
    const float* cls_w3    = (const float*)d_in[11];
    const float* cls_b3    = (const float*)d_in[12];
    const float* reg_w1    = (const float*)d_in[13];
    const float* reg_b1    = (const float*)d_in[14];
    const float* reg_w2    = (const float*)d_in[15];
    const float* reg_b2    = (const float*)d_in[16];
    const float* reg_w3    = (const float*)d_in[17];
    const float* reg_b3    = (const float*)d_in[18];
    float* out = (float*)d_out;

    dim3 grid(MM / 64, 2, L6);   // 450 x {cls,reg} x 6 levels
    fused_mlp_kernel<<<grid, 256>>>(0, hs, cls_w1, cls_b1, ln1_g, ln1_b, reg_w1, reg_b1);
    fused_mlp_kernel<<<grid, 256>>>(1, hs, cls_w2, cls_b2, ln2_g, ln2_b, reg_w2, reg_b2);
    head_kernel<<<L6 * (MM / 8), 256>>>(cls_w3, cls_b3, reg_w3, reg_b3,
                                        init_ref, inter_ref, out);
}